// round 14
// baseline (speedup 1.0000x reference)
#include <cuda_runtime.h>
#include <math.h>

#define NB 16
#define NL 128
#define NH 256
#define ND 300
#define NE 34
#define NA 36

__device__ float d_zx[2][NL][NB][4*NH];
__device__ float d_hidden[NB][NL][2*NH];
__device__ float d_S [NB][NL][NA];
__device__ float d_T [NB][NL][NA];
__device__ float d_E0[NB][NL][NE];
__device__ int   d_evp[NB][NL];
// tagged h exchange: [dir][sub][parity][word] = {h0,h1,tag,pad}
__device__ uint4 g_hslot[2][64][2][32];

__device__ __forceinline__ float sigf(float x){ return 1.f/(1.f + expf(-x)); }
__device__ __forceinline__ unsigned ordk(float v){
    unsigned u = __float_as_uint(v);
    return (u & 0x80000000u) ? ~u : (u | 0x80000000u);
}
__device__ __forceinline__ unsigned ldvol(const unsigned* p){
    unsigned v;
    asm volatile("ld.volatile.global.u32 %0, [%1];" : "=r"(v) : "l"(p));
    return v;
}
__device__ __forceinline__ uint4 ldvol4(const uint4* p){
    uint4 v;
    asm volatile("ld.volatile.global.v4.u32 {%0,%1,%2,%3}, [%4];"
                 : "=r"(v.x), "=r"(v.y), "=r"(v.z), "=r"(v.w) : "l"(p));
    return v;
}
__device__ __forceinline__ void stvol4(uint4* p, unsigned a, unsigned b,
                                       unsigned c, unsigned d){
    asm volatile("st.volatile.global.v4.u32 [%0], {%1,%2,%3,%4};"
                 :: "l"(p), "r"(a), "r"(b), "r"(c), "r"(d));
}
__device__ __forceinline__ unsigned long long ffma2(unsigned long long a,
        unsigned long long b, unsigned long long c){
    unsigned long long d;
    asm("fma.rn.f32x2 %0, %1, %2, %3;" : "=l"(d) : "l"(a), "l"(b), "l"(c));
    return d;
}
__device__ __forceinline__ float hsum2(unsigned long long v){
    unsigned lo, hi;
    asm("mov.b64 {%0,%1}, %2;" : "=r"(lo), "=r"(hi) : "l"(v));
    return __uint_as_float(lo) + __uint_as_float(hi);
}
__device__ __forceinline__ void unpk2(unsigned long long v, float& lo, float& hi){
    unsigned a, b;
    asm("mov.b64 {%0,%1}, %2;" : "=r"(a), "=r"(b) : "l"(v));
    lo = __uint_as_float(a); hi = __uint_as_float(b);
}

// no-op kernel: keeps the ncu profiled-launch slot on k2 (diagnostic)
__global__ void k0_nop() {}

// ============================================================================
// K1: zx = gather(emb, ids) @ Wih^T + (bih+bhh). FFMA2 + double-buffered smem
// (register prefetch of tile kt+1 overlaps compute of kt; 1 sync per iter).
// ============================================================================
__global__ void __launch_bounds__(256) k1_zx(const int* __restrict__ ids,
        const float* __restrict__ emb,
        const float* __restrict__ WihF, const float* __restrict__ WihB,
        const float* __restrict__ bihF, const float* __restrict__ bhhF,
        const float* __restrict__ bihB, const float* __restrict__ bhhB)
{
    __shared__ __align__(16) float As [2][16][68];
    __shared__ __align__(16) float Bs2[2][16][136];
    __shared__ int ids_s[64];
    const int tid = threadIdx.x;
    const int m0 = blockIdx.y * 64;
    const int n0 = blockIdx.x * 64;
    if (tid < 64) ids_s[tid] = ids[m0 + tid];
    __syncthreads();
    const int lm = tid & 63;
    const int k4 = tid >> 6;
    const int ty = tid >> 4;
    const int tx = tid & 15;
    const float* arow = emb;   // row chosen per-load via ids_s
    const float* brow = ( (n0 + lm) < 1024 ) ? (WihF + (long)(n0+lm)*ND)
                                             : (WihB + (long)(n0+lm-1024)*ND);
    const float* aro = emb + (long)ids_s[lm]*ND;

    float av[4], bv[4];
    // load tile kt into regs
    auto LOADT = [&](int kt){
        const int k0 = kt*16 + k4*4;
        if (k0 + 3 < ND){
            float4 t4 = *(const float4*)(aro + k0);
            av[0]=t4.x; av[1]=t4.y; av[2]=t4.z; av[3]=t4.w;
            float4 u4 = *(const float4*)(brow + k0);
            bv[0]=u4.x; bv[1]=u4.y; bv[2]=u4.z; bv[3]=u4.w;
        } else {
            #pragma unroll
            for (int c=0;c<4;c++){
                av[c] = (k0+c < ND) ? aro [k0+c] : 0.f;
                bv[c] = (k0+c < ND) ? brow[k0+c] : 0.f;
            }
        }
    };
    auto STORET = [&](int buf){
        #pragma unroll
        for (int c=0;c<4;c++){
            As[buf][k4*4+c][lm] = av[c];
            *(float2*)&Bs2[buf][k4*4+c][2*lm] = make_float2(bv[c], bv[c]);
        }
    };

    unsigned long long acc2[2][4];
    #pragma unroll
    for (int p=0;p<2;p++)
        #pragma unroll
        for (int j=0;j<4;j++) acc2[p][j] = 0ull;

    LOADT(0);
    STORET(0);
    __syncthreads();

    for (int kt = 0; kt < 19; kt++) {
        const int cur = kt & 1;
        if (kt < 18) LOADT(kt+1);
        #pragma unroll
        for (int kk = 0; kk < 16; kk++) {
            const ulonglong2 a2  = *(const ulonglong2*)&As [cur][kk][ty*4];
            const ulonglong2 b01 = *(const ulonglong2*)&Bs2[cur][kk][tx*8];
            const ulonglong2 b23 = *(const ulonglong2*)&Bs2[cur][kk][tx*8+4];
            acc2[0][0] = ffma2(a2.x, b01.x, acc2[0][0]);
            acc2[0][1] = ffma2(a2.x, b01.y, acc2[0][1]);
            acc2[0][2] = ffma2(a2.x, b23.x, acc2[0][2]);
            acc2[0][3] = ffma2(a2.x, b23.y, acc2[0][3]);
            acc2[1][0] = ffma2(a2.y, b01.x, acc2[1][0]);
            acc2[1][1] = ffma2(a2.y, b01.y, acc2[1][1]);
            acc2[1][2] = ffma2(a2.y, b23.x, acc2[1][2]);
            acc2[1][3] = ffma2(a2.y, b23.y, acc2[1][3]);
        }
        if (kt < 18) STORET(1 - cur);
        __syncthreads();
    }

    float acc[4][4];
    #pragma unroll
    for (int p=0;p<2;p++)
        #pragma unroll
        for (int j=0;j<4;j++) unpk2(acc2[p][j], acc[2*p][j], acc[2*p+1][j]);
    #pragma unroll
    for (int jj=0;jj<4;jj++){
        const int n = n0 + tx*4 + jj;
        const float bias = (n < 1024) ? (bihF[n] + bhhF[n]) : (bihB[n-1024] + bhhB[n-1024]);
        #pragma unroll
        for (int i=0;i<4;i++){
            const int m = m0 + ty*4 + i;
            const int bb = m >> 7, t = m & 127;
            const float v = acc[i][jj] + bias;
            if (n < 1024) d_zx[0][t][bb][n]      = v;
            else          d_zx[1][t][bb][n-1024] = v;
        }
    }
}

// ============================================================================
// K2: persistent BiLSTM, sync-domain = 8 blocks.
// Partition: dir (2) x batch-group (8 groups of 2 batches) x unit-block
// (8 blocks of 32 units). A block polls only its group's 8 producers.
// Whh slice (128 rows x 256) resident in smem; tagged parity exchange.
// ============================================================================
__global__ void __launch_bounds__(512) k2_lstm(const float* __restrict__ WhhF,
                                               const float* __restrict__ WhhB)
{
    __shared__ __align__(16) float W_s[128][260];   // 133 KB
    __shared__ __align__(16) float h_s[2][256];
    __shared__ float zp[128][4];
    const int tid = threadIdx.x;
    const int bx  = blockIdx.x;
    const int dir = bx >> 6;
    const int sub = bx & 63;
    const int g2  = sub >> 3;       // batch group (batches g2*2, g2*2+1)
    const int ub  = sub & 7;        // unit block (units ub*32 .. +31)
    const int u0  = ub * 32;
    const int batch0 = g2 * 2;
    const float* Whh = dir ? WhhB : WhhF;

    // load W slice: local row r = g*32 + ul  ->  global row g*256 + u0 + ul
    for (int idx = tid; idx < 128*256; idx += 512){
        const int r = idx >> 8, k = idx & 255;
        const int g = r >> 5, ul = r & 31;
        W_s[r][k] = Whh[(long)(g*256 + u0 + ul)*256 + k];
    }

    // dot mapping: warp w covers rows w*8..w*8+7
    const int w    = tid >> 5, lane = tid & 31;
    const int rlow = lane >> 2;
    const int db   = (lane >> 1) & 1;   // batch (local)
    const int kh   = lane & 1;          // k half
    const int r    = w*8 + rlow;

    // gates mapping (tid<256): cell = ul*2 + bl, 4 threads per cell
    const int gg = tid & 3, cell = tid >> 2;
    const int gul = cell >> 1, gbl = cell & 1;
    float creg = 0.f;

    const uint4* src = &g_hslot[dir][g2*8 + w][0][lane];   // valid for w<8
    const unsigned G0 = ldvol(&((const unsigned*)&g_hslot[dir][sub][0][0])[2]);
    __syncthreads();

    for (unsigned t = 0; t < NL; t++){
        const int xt = dir ? (NL-1-(int)t) : (int)t;

        // prefetch zx (overlaps poll)
        float zxv = 0.f;
        if (tid < 256)
            zxv = __ldg(&d_zx[dir][xt][batch0 + gbl][gg*256 + u0 + gul]);

        if (t > 0){
            if (w < 8){
                const unsigned want = G0 + t;
                const int po = (t & 1) * 32;
                uint4 v;
                while (true){
                    v = ldvol4(src + po);
                    if (__all_sync(0xffffffffu, (int)(v.z - want) >= 0)) break;
                }
                h_s[0][w*32 + lane] = __uint_as_float(v.x);
                h_s[1][w*32 + lane] = __uint_as_float(v.y);
            }
        } else {
            h_s[tid >> 8][tid & 255] = 0.f;
        }
        __syncthreads();

        // dot: thread = (row r, batch db, k-half kh): 128 k values, ffma2
        {
            const ulonglong2* hp = (const ulonglong2*)&h_s[db][kh*128];
            const ulonglong2* wp = (const ulonglong2*)&W_s[r][kh*128];
            unsigned long long a0 = 0ull, a1 = 0ull;
            #pragma unroll
            for (int i=0;i<32;i++){
                const ulonglong2 h2 = hp[i];
                const ulonglong2 w2 = wp[i];
                a0 = ffma2(h2.x, w2.x, a0);
                a1 = ffma2(h2.y, w2.y, a1);
            }
            zp[r][db*2 + kh] = hsum2(a0) + hsum2(a1);
        }
        __syncthreads();

        // gates (4 threads/cell) + in-warp fused publish
        if (tid < 256){
            const float* q = &zp[gg*32 + gul][gbl*2];
            const float z = zxv + (q[0] + q[1]);
            const float nl = (gg == 2) ? tanhf(z) : sigf(z);
            const float nf = __shfl_down_sync(0xffffffffu, nl, 1);
            const float ng = __shfl_down_sync(0xffffffffu, nl, 2);
            const float no = __shfl_down_sync(0xffffffffu, nl, 3);
            float h = 0.f;
            if (gg == 0){
                creg = nf*creg + nl*ng;
                h = no * tanhf(creg);
                d_hidden[batch0 + gbl][xt][dir*NH + u0 + gul] = h;
            }
            const float hn = __shfl_down_sync(0xffffffffu, h, 4);
            if ((tid & 7) == 0){
                stvol4(&g_hslot[dir][sub][(t+1)&1][tid >> 3],
                       __float_as_uint(h), __float_as_uint(hn), G0 + t + 1u, 0u);
            }
        }
    }
}

// ============================================================================
// K3: per-token static decode projections S, T, E0.
// ============================================================================
__global__ void __launch_bounds__(128) k3_pre(const float* __restrict__ Wa,
        const float* __restrict__ We,
        const float* __restrict__ ba, const float* __restrict__ be)
{
    __shared__ __align__(16) float hid_s[8][516];
    const int tid = threadIdx.x;
    const int m0 = blockIdx.x * 8;
    const float* hbase = &d_hidden[0][0][0] + (long)m0 * 512;
    for (int idx = tid; idx < 8*512; idx += 128)
        hid_s[idx >> 9][idx & 511] = hbase[idx];
    __syncthreads();
    const int tok = tid >> 4, slot = tid & 15;
    const int m = m0 + tok;
    const float* hv = hid_s[tok];
    for (int cc = slot; cc < 106; cc += 16){
        float acc = 0.f;
        if (cc < 72){
            const float* wr = Wa + (long)(cc < 36 ? cc : cc-36) * 1092 + (cc < 36 ? 0 : 512);
            #pragma unroll 4
            for (int k = 0; k < 512; k += 4){
                const float4 w4 = *(const float4*)(wr + k);
                const float4 h4 = *(const float4*)(hv + k);
                acc = fmaf(h4.x, w4.x, acc);
                acc = fmaf(h4.y, w4.y, acc);
                acc = fmaf(h4.z, w4.z, acc);
                acc = fmaf(h4.w, w4.w, acc);
            }
            if (cc < 36) { acc += ba[cc]; (&d_S[0][0][0])[(long)m*36 + cc]      = acc; }
            else         {               (&d_T[0][0][0])[(long)m*36 + (cc-36)] = acc; }
        } else {
            const int e = cc - 72;
            const float* wr = We + (long)e * 545;
            #pragma unroll 4
            for (int k = 0; k < 512; k += 4){
                acc = fmaf(hv[k+0], wr[k+0], acc);
                acc = fmaf(hv[k+1], wr[k+1], acc);
                acc = fmaf(hv[k+2], wr[k+2], acc);
                acc = fmaf(hv[k+3], wr[k+3], acc);
            }
            acc += be[e];
            (&d_E0[0][0][0])[(long)m*34 + e] = acc;
        }
    }
}

// ============================================================================
// K3b: sequential event scan. 16 blocks x 32 threads (one warp per batch).
// ============================================================================
__global__ void __launch_bounds__(32) k3b_event(const float* __restrict__ We,
        float* __restrict__ evout)
{
    __shared__ float Weg_s[33][34];
    const int lane = threadIdx.x;
    const int b = blockIdx.x;
    for (int idx = lane; idx < 33*34; idx += 32){
        const int k = idx / 34, e = idx % 34;
        Weg_s[k][e] = We[(long)e*545 + 512 + k];
    }
    __syncwarp();

    const float* E0b = &d_E0[b][0][0];
    float gtA = 0.f, gtB = 0.f;
    unsigned long long gtrg = 0ull;
    const int tail = (lane < 2) ? (32 + lane) : 33;
    float e0a = __ldg(E0b + lane);
    float e0b = __ldg(E0b + tail);

    for (int i = 0; i < NL; i++){
        float e0a_n = 0.f, e0b_n = 0.f;
        if (i < NL-1){
            e0a_n = __ldg(E0b + (i+1)*34 + lane);
            e0b_n = __ldg(E0b + (i+1)*34 + tail);
        }
        const float va = e0a + gtA;
        const float vb = (lane < 2) ? (e0b + gtB) : -3.0e38f;
        evout[((long)b*NL + i)*NE + lane] = va;
        if (lane < 2) evout[((long)b*NL + i)*NE + 32 + lane] = vb;
        const unsigned ka = ordk(va);
        const unsigned mx = __reduce_max_sync(0xffffffffu, ka);
        const unsigned ball = __ballot_sync(0xffffffffu, ka == mx);
        const int am0 = __ffs(ball) - 1;
        float bv = __shfl_sync(0xffffffffu, va, am0);
        int ame = am0;
        const float v32 = __shfl_sync(0xffffffffu, vb, 0);
        const float v33 = __shfl_sync(0xffffffffu, vb, 1);
        if (v32 > bv){ bv = v32; ame = 32; }
        if (v33 > bv){ bv = v33; ame = 33; }
        int ne = 0;
        if (ame > 0 && !((gtrg >> (ame-1)) & 1ull)){ gtrg |= 1ull << (ame-1); ne = 1; }
        if (lane == 0) d_evp[b][i] = ame;
        if (ne){
            gtA += Weg_s[ame-1][lane];
            if (lane < 2) gtB += Weg_s[ame-1][32+lane];
        }
        e0a = e0a_n; e0b = e0b_n;
    }
}

// ============================================================================
// K4: arg decode, pure parallel consumer. 16 blocks x 128 threads.
// ============================================================================
__global__ void __launch_bounds__(128) k4_scan(const float* __restrict__ Wa,
        float* __restrict__ argout)
{
    __shared__ __align__(16) float Ts[NL][NA];
    __shared__ float Wag1_s[35][36];
    __shared__ float Wag2_s[33][36];
    __shared__ int evp_s[NL];

    const int tid = threadIdx.x;
    const int b = blockIdx.x;
    for (int idx = tid; idx < NL*NA; idx += 128) (&Ts[0][0])[idx] = (&d_T[b][0][0])[idx];
    for (int idx = tid; idx < 35*36; idx += 128){
        const int k = idx / 36, a = idx % 36;
        Wag1_s[k][a] = Wa[(long)a*1092 + 1024 + k];
    }
    for (int idx = tid; idx < 33*36; idx += 128){
        const int k = idx / 36, a = idx % 36;
        Wag2_s[k][a] = Wa[(long)a*1092 + 1059 + k];
    }
    if (tid < NL) evp_s[tid] = d_evp[b][tid];

    const int j = tid;
    float SG[36];
    {
        const float4* sp = (const float4*)&d_S[b][j][0];
        #pragma unroll
        for (int q=0;q<9;q++){
            const float4 v = sp[q];
            SG[q*4+0]=v.x; SG[q*4+1]=v.y; SG[q*4+2]=v.z; SG[q*4+3]=v.w;
        }
    }
    unsigned long long garg = 0ull, gta = 0ull;
    __syncthreads();

    for (int i = 0; i < NL; i++){
        const int ep = evp_s[i];
        const float* Ti = &Ts[i][0];
        float* op = argout + (((long)b*NL + i)*NL + j)*NA;
        int am = 0; float bm = -1e30f;
        #pragma unroll
        for (int a4 = 0; a4 < 9; a4++){
            const float v0 = SG[a4*4+0] + Ti[a4*4+0];
            const float v1 = SG[a4*4+1] + Ti[a4*4+1];
            const float v2 = SG[a4*4+2] + Ti[a4*4+2];
            const float v3 = SG[a4*4+3] + Ti[a4*4+3];
            if (v0 > bm){ bm = v0; am = a4*4+0; }
            if (v1 > bm){ bm = v1; am = a4*4+1; }
            if (v2 > bm){ bm = v2; am = a4*4+2; }
            if (v3 > bm){ bm = v3; am = a4*4+3; }
            float4 v4; v4.x=v0; v4.y=v1; v4.z=v2; v4.w=v3;
            *(float4*)(op + a4*4) = v4;
        }
        if (ep > 0 && am > 0){
            const int ke = ep - 1;
            if (!((gta >> ke) & 1ull)){
                gta |= 1ull << ke;
                #pragma unroll
                for (int a=0;a<36;a++) SG[a] += Wag2_s[ke][a];
            }
            const int ak = am - 1;
            if (!((garg >> ak) & 1ull)){
                garg |= 1ull << ak;
                #pragma unroll
                for (int a=0;a<36;a++) SG[a] += Wag1_s[ak][a];
            }
        }
    }
}

extern "C" void kernel_launch(void* const* d_in, const int* in_sizes, int n_in,
                              void* d_out, int out_size)
{
    const int*   ids  = (const int*)  d_in[0];
    const float* emb  = (const float*)d_in[1];
    const float* WihF = (const float*)d_in[2];
    const float* WhhF = (const float*)d_in[3];
    const float* bihF = (const float*)d_in[4];
    const float* bhhF = (const float*)d_in[5];
    const float* WihB = (const float*)d_in[6];
    const float* WhhB = (const float*)d_in[7];
    const float* bihB = (const float*)d_in[8];
    const float* bhhB = (const float*)d_in[9];
    const float* We   = (const float*)d_in[10];
    const float* be   = (const float*)d_in[11];
    const float* Wa   = (const float*)d_in[12];
    const float* ba   = (const float*)d_in[13];
    float* out    = (float*)d_out;
    float* evout  = out;
    float* argout = out + (long)NB*NL*NE;

    cudaFuncSetAttribute(k2_lstm, cudaFuncAttributeMaxDynamicSharedMemorySize, 0);
    k1_zx<<<dim3(32, 32), 256>>>(ids, emb, WihF, WihB, bihF, bhhF, bihB, bhhB);
    k0_nop<<<1, 1>>>();
    k0_nop<<<1, 1>>>();
    k2_lstm<<<128, 512>>>(WhhF, WhhB);
    k3_pre<<<256, 128>>>(Wa, We, ba, be);
    k3b_event<<<16, 32>>>(We, evout);
    k4_scan<<<16, 128>>>(Wa, argout);
}

// round 15
// speedup vs baseline: 1.6570x; 1.6570x over previous
#include <cuda_runtime.h>
#include <math.h>

#define NB 16
#define NL 128
#define NH 256
#define ND 300
#define NE 34
#define NA 36

__device__ float d_zx[2][NL][NB][4*NH];
__device__ float d_hidden[NB][NL][2*NH];
__device__ float d_S [NB][NL][NA];
__device__ float d_T [NB][NL][NA];
__device__ float d_E0[NB][NL][NE];
__device__ int   d_evp[NB][NL];
// tagged h exchange: [dir][sub][parity][word] = {h0,h1,tag,pad}
__device__ uint4 g_hslot[2][64][2][32];

__device__ __forceinline__ float sigf(float x){ return 1.f/(1.f + expf(-x)); }
__device__ __forceinline__ unsigned ordk(float v){
    unsigned u = __float_as_uint(v);
    return (u & 0x80000000u) ? ~u : (u | 0x80000000u);
}
__device__ __forceinline__ unsigned ldvol(const unsigned* p){
    unsigned v;
    asm volatile("ld.volatile.global.u32 %0, [%1];" : "=r"(v) : "l"(p));
    return v;
}
__device__ __forceinline__ uint4 ldvol4(const uint4* p){
    uint4 v;
    asm volatile("ld.volatile.global.v4.u32 {%0,%1,%2,%3}, [%4];"
                 : "=r"(v.x), "=r"(v.y), "=r"(v.z), "=r"(v.w) : "l"(p));
    return v;
}
__device__ __forceinline__ void stvol4(uint4* p, unsigned a, unsigned b,
                                       unsigned c, unsigned d){
    asm volatile("st.volatile.global.v4.u32 [%0], {%1,%2,%3,%4};"
                 :: "l"(p), "r"(a), "r"(b), "r"(c), "r"(d));
}
__device__ __forceinline__ unsigned long long ffma2(unsigned long long a,
        unsigned long long b, unsigned long long c){
    unsigned long long d;
    asm("fma.rn.f32x2 %0, %1, %2, %3;" : "=l"(d) : "l"(a), "l"(b), "l"(c));
    return d;
}
__device__ __forceinline__ float hsum2(unsigned long long v){
    unsigned lo, hi;
    asm("mov.b64 {%0,%1}, %2;" : "=r"(lo), "=r"(hi) : "l"(v));
    return __uint_as_float(lo) + __uint_as_float(hi);
}
__device__ __forceinline__ void unpk2(unsigned long long v, float& lo, float& hi){
    unsigned a, b;
    asm("mov.b64 {%0,%1}, %2;" : "=r"(a), "=r"(b) : "l"(v));
    lo = __uint_as_float(a); hi = __uint_as_float(b);
}

// no-op kernel: shifts the ncu profiled-launch slot (index 3) onto k1
__global__ void k0_nop() {}

// ============================================================================
// K1: zx = gather(emb, ids) @ Wih^T + (bih+bhh). FFMA2 + double-buffered smem.
// ============================================================================
__global__ void __launch_bounds__(256) k1_zx(const int* __restrict__ ids,
        const float* __restrict__ emb,
        const float* __restrict__ WihF, const float* __restrict__ WihB,
        const float* __restrict__ bihF, const float* __restrict__ bhhF,
        const float* __restrict__ bihB, const float* __restrict__ bhhB)
{
    __shared__ __align__(16) float As [2][16][68];
    __shared__ __align__(16) float Bs2[2][16][136];
    __shared__ int ids_s[64];
    const int tid = threadIdx.x;
    const int m0 = blockIdx.y * 64;
    const int n0 = blockIdx.x * 64;
    if (tid < 64) ids_s[tid] = ids[m0 + tid];
    __syncthreads();
    const int lm = tid & 63;
    const int k4 = tid >> 6;
    const int ty = tid >> 4;
    const int tx = tid & 15;
    const float* brow = ( (n0 + lm) < 1024 ) ? (WihF + (long)(n0+lm)*ND)
                                             : (WihB + (long)(n0+lm-1024)*ND);
    const float* aro = emb + (long)ids_s[lm]*ND;

    float av[4], bv[4];
    auto LOADT = [&](int kt){
        const int k0 = kt*16 + k4*4;
        if (k0 + 3 < ND){
            float4 t4 = *(const float4*)(aro + k0);
            av[0]=t4.x; av[1]=t4.y; av[2]=t4.z; av[3]=t4.w;
            float4 u4 = *(const float4*)(brow + k0);
            bv[0]=u4.x; bv[1]=u4.y; bv[2]=u4.z; bv[3]=u4.w;
        } else {
            #pragma unroll
            for (int c=0;c<4;c++){
                av[c] = (k0+c < ND) ? aro [k0+c] : 0.f;
                bv[c] = (k0+c < ND) ? brow[k0+c] : 0.f;
            }
        }
    };
    auto STORET = [&](int buf){
        #pragma unroll
        for (int c=0;c<4;c++){
            As[buf][k4*4+c][lm] = av[c];
            *(float2*)&Bs2[buf][k4*4+c][2*lm] = make_float2(bv[c], bv[c]);
        }
    };

    unsigned long long acc2[2][4];
    #pragma unroll
    for (int p=0;p<2;p++)
        #pragma unroll
        for (int j=0;j<4;j++) acc2[p][j] = 0ull;

    LOADT(0);
    STORET(0);
    __syncthreads();

    for (int kt = 0; kt < 19; kt++) {
        const int cur = kt & 1;
        if (kt < 18) LOADT(kt+1);
        #pragma unroll
        for (int kk = 0; kk < 16; kk++) {
            const ulonglong2 a2  = *(const ulonglong2*)&As [cur][kk][ty*4];
            const ulonglong2 b01 = *(const ulonglong2*)&Bs2[cur][kk][tx*8];
            const ulonglong2 b23 = *(const ulonglong2*)&Bs2[cur][kk][tx*8+4];
            acc2[0][0] = ffma2(a2.x, b01.x, acc2[0][0]);
            acc2[0][1] = ffma2(a2.x, b01.y, acc2[0][1]);
            acc2[0][2] = ffma2(a2.x, b23.x, acc2[0][2]);
            acc2[0][3] = ffma2(a2.x, b23.y, acc2[0][3]);
            acc2[1][0] = ffma2(a2.y, b01.x, acc2[1][0]);
            acc2[1][1] = ffma2(a2.y, b01.y, acc2[1][1]);
            acc2[1][2] = ffma2(a2.y, b23.x, acc2[1][2]);
            acc2[1][3] = ffma2(a2.y, b23.y, acc2[1][3]);
        }
        if (kt < 18) STORET(1 - cur);
        __syncthreads();
    }

    float acc[4][4];
    #pragma unroll
    for (int p=0;p<2;p++)
        #pragma unroll
        for (int j=0;j<4;j++) unpk2(acc2[p][j], acc[2*p][j], acc[2*p+1][j]);
    #pragma unroll
    for (int jj=0;jj<4;jj++){
        const int n = n0 + tx*4 + jj;
        const float bias = (n < 1024) ? (bihF[n] + bhhF[n]) : (bihB[n-1024] + bhhB[n-1024]);
        #pragma unroll
        for (int i=0;i<4;i++){
            const int m = m0 + ty*4 + i;
            const int bb = m >> 7, t = m & 127;
            const float v = acc[i][jj] + bias;
            if (n < 1024) d_zx[0][t][bb][n]      = v;
            else          d_zx[1][t][bb][n-1024] = v;
        }
    }
}

// ============================================================================
// K2: persistent BiLSTM (R13 structure — measured 337.9us). 128 blocks
// (dir = bx>>6, 4 units) x 512 threads. Tagged {h0,h1,tag} exchange published
// in-warp right after gates; gates parallelized 4-threads-per-cell.
// ============================================================================
__global__ void __launch_bounds__(512) k2_lstm(const float* __restrict__ WhhF,
                                               const float* __restrict__ WhhB)
{
    __shared__ __align__(16) float W_s[16][260];
    __shared__ __align__(16) float h_s[16][260];
    __shared__ float zp[16][16][8];
    const int tid = threadIdx.x;
    const int bx  = blockIdx.x;
    const int dir = bx >> 6;
    const int sub = bx & 63;
    const int u0  = sub * 4;
    const float* Whh = dir ? WhhB : WhhF;

    for (int idx = tid; idx < 16*256; idx += 512){
        const int rl = idx >> 8, k = idx & 255;
        const int rg = (rl >> 2) * 256 + u0 + (rl & 3);
        W_s[rl][k] = Whh[(long)rg*256 + k];
    }

    const int lane = tid & 31, w = tid >> 5;   // 16 warps
    const int bdot = lane & 15;
    const int rq   = (lane >> 4) + 2*(w & 1);
    const int kq   = w >> 1;

    // gates mapping (tid < 256): pair p = tid>>2 (b = p>>2, cu = p&3), gate g = tid&3
    const int gp = tid >> 2, gg = tid & 3;
    const int gb = gp >> 2, gcu = gp & 3;
    float creg = 0.f;

    // poll precompute: warp w owns producers 4w..4w+3; lane handles word `lane`
    const uint4* srcp[4];
    float2* dstp[4];
    #pragma unroll
    for (int r=0;r<4;r++){
        srcp[r] = &g_hslot[dir][4*w + r][0][lane];
        dstp[r] = (float2*)&h_s[lane >> 1][(4*w + r)*4 + (lane & 1)*2];
    }

    const unsigned G0 = ldvol(&((const unsigned*)&g_hslot[dir][sub][0][0])[2]);
    __syncthreads();

    for (unsigned t = 0; t < NL; t++){
        const int xt = dir ? (NL-1-(int)t) : (int)t;

        // prefetch this step's zx for my gate (overlaps the poll)
        float zxv = 0.f;
        if (tid < 256)
            zxv = __ldg(&d_zx[dir][xt][gb][gg*256 + u0 + gcu]);

        if (t > 0){
            const unsigned want = G0 + t;
            const int po = (t & 1) * 32;
            uint4 v0, v1, v2, v3;
            while (true){
                v0 = ldvol4(srcp[0] + po);
                v1 = ldvol4(srcp[1] + po);
                v2 = ldvol4(srcp[2] + po);
                v3 = ldvol4(srcp[3] + po);
                const bool ok = ((int)(v0.z - want) >= 0) & ((int)(v1.z - want) >= 0)
                              & ((int)(v2.z - want) >= 0) & ((int)(v3.z - want) >= 0);
                if (__all_sync(0xffffffffu, ok)) break;
            }
            *dstp[0] = make_float2(__uint_as_float(v0.x), __uint_as_float(v0.y));
            *dstp[1] = make_float2(__uint_as_float(v1.x), __uint_as_float(v1.y));
            *dstp[2] = make_float2(__uint_as_float(v2.x), __uint_as_float(v2.y));
            *dstp[3] = make_float2(__uint_as_float(v3.x), __uint_as_float(v3.y));
        } else {
            for (int idx = tid; idx < 16*256; idx += 512)
                h_s[idx >> 8][idx & 255] = 0.f;
        }
        __syncthreads();

        // dot: 4 rows x 1 batch x 32 k per thread; ffma2 on 16B loads
        {
            const ulonglong2* hp2 = (const ulonglong2*)&h_s[bdot][kq*32];
            ulonglong2 h2[8];
            #pragma unroll
            for (int i=0;i<8;i++) h2[i] = hp2[i];
            unsigned long long a2[4] = {0ull,0ull,0ull,0ull};
            #pragma unroll
            for (int i=0;i<8;i++){
                #pragma unroll
                for (int rr=0;rr<4;rr++){
                    const ulonglong2 w2 = ((const ulonglong2*)&W_s[rq*4+rr][kq*32])[i];
                    a2[rr] = ffma2(h2[i].x, w2.x, a2[rr]);
                    a2[rr] = ffma2(h2[i].y, w2.y, a2[rr]);
                }
            }
            #pragma unroll
            for (int rr=0;rr<4;rr++) zp[rq*4+rr][bdot][kq] = hsum2(a2[rr]);
        }
        __syncthreads();

        // gates (4 threads/cell) + in-warp fused publish
        if (tid < 256){
            const float* q = zp[gg*4 + gcu][gb];
            const float z = zxv + (((q[0]+q[1]) + (q[2]+q[3])) + ((q[4]+q[5]) + (q[6]+q[7])));
            const float nl = (gg == 2) ? tanhf(z) : sigf(z);
            const float nf = __shfl_down_sync(0xffffffffu, nl, 1);   // sig(f)
            const float ng = __shfl_down_sync(0xffffffffu, nl, 2);   // tanh(g)
            const float no = __shfl_down_sync(0xffffffffu, nl, 3);   // sig(o)
            float h = 0.f;
            if (gg == 0){
                creg = nf*creg + nl*ng;
                h = no * tanhf(creg);
                d_hidden[gb][xt][dir*NH + u0 + gcu] = h;
            }
            const float hn = __shfl_down_sync(0xffffffffu, h, 4);
            if ((tid & 7) == 0){
                stvol4(&g_hslot[dir][sub][(t+1)&1][tid >> 3],
                       __float_as_uint(h), __float_as_uint(hn), G0 + t + 1u, 0u);
            }
        }
    }
}

// ============================================================================
// K3: per-token static decode projections S, T, E0.
// ============================================================================
__global__ void __launch_bounds__(128) k3_pre(const float* __restrict__ Wa,
        const float* __restrict__ We,
        const float* __restrict__ ba, const float* __restrict__ be)
{
    __shared__ __align__(16) float hid_s[8][516];
    const int tid = threadIdx.x;
    const int m0 = blockIdx.x * 8;
    const float* hbase = &d_hidden[0][0][0] + (long)m0 * 512;
    for (int idx = tid; idx < 8*512; idx += 128)
        hid_s[idx >> 9][idx & 511] = hbase[idx];
    __syncthreads();
    const int tok = tid >> 4, slot = tid & 15;
    const int m = m0 + tok;
    const float* hv = hid_s[tok];
    for (int cc = slot; cc < 106; cc += 16){
        float acc = 0.f;
        if (cc < 72){
            const float* wr = Wa + (long)(cc < 36 ? cc : cc-36) * 1092 + (cc < 36 ? 0 : 512);
            #pragma unroll 4
            for (int k = 0; k < 512; k += 4){
                const float4 w4 = *(const float4*)(wr + k);
                const float4 h4 = *(const float4*)(hv + k);
                acc = fmaf(h4.x, w4.x, acc);
                acc = fmaf(h4.y, w4.y, acc);
                acc = fmaf(h4.z, w4.z, acc);
                acc = fmaf(h4.w, w4.w, acc);
            }
            if (cc < 36) { acc += ba[cc]; (&d_S[0][0][0])[(long)m*36 + cc]      = acc; }
            else         {               (&d_T[0][0][0])[(long)m*36 + (cc-36)] = acc; }
        } else {
            const int e = cc - 72;
            const float* wr = We + (long)e * 545;
            #pragma unroll 4
            for (int k = 0; k < 512; k += 4){
                acc = fmaf(hv[k+0], wr[k+0], acc);
                acc = fmaf(hv[k+1], wr[k+1], acc);
                acc = fmaf(hv[k+2], wr[k+2], acc);
                acc = fmaf(hv[k+3], wr[k+3], acc);
            }
            acc += be[e];
            (&d_E0[0][0][0])[(long)m*34 + e] = acc;
        }
    }
}

// ============================================================================
// K3b: sequential event scan. 16 blocks x 32 threads (one warp per batch).
// ============================================================================
__global__ void __launch_bounds__(32) k3b_event(const float* __restrict__ We,
        float* __restrict__ evout)
{
    __shared__ float Weg_s[33][34];
    const int lane = threadIdx.x;
    const int b = blockIdx.x;
    for (int idx = lane; idx < 33*34; idx += 32){
        const int k = idx / 34, e = idx % 34;
        Weg_s[k][e] = We[(long)e*545 + 512 + k];
    }
    __syncwarp();

    const float* E0b = &d_E0[b][0][0];
    float gtA = 0.f, gtB = 0.f;
    unsigned long long gtrg = 0ull;
    const int tail = (lane < 2) ? (32 + lane) : 33;
    float e0a = __ldg(E0b + lane);
    float e0b = __ldg(E0b + tail);

    for (int i = 0; i < NL; i++){
        float e0a_n = 0.f, e0b_n = 0.f;
        if (i < NL-1){
            e0a_n = __ldg(E0b + (i+1)*34 + lane);
            e0b_n = __ldg(E0b + (i+1)*34 + tail);
        }
        const float va = e0a + gtA;
        const float vb = (lane < 2) ? (e0b + gtB) : -3.0e38f;
        evout[((long)b*NL + i)*NE + lane] = va;
        if (lane < 2) evout[((long)b*NL + i)*NE + 32 + lane] = vb;
        const unsigned ka = ordk(va);
        const unsigned mx = __reduce_max_sync(0xffffffffu, ka);
        const unsigned ball = __ballot_sync(0xffffffffu, ka == mx);
        const int am0 = __ffs(ball) - 1;
        float bv = __shfl_sync(0xffffffffu, va, am0);
        int ame = am0;
        const float v32 = __shfl_sync(0xffffffffu, vb, 0);
        const float v33 = __shfl_sync(0xffffffffu, vb, 1);
        if (v32 > bv){ bv = v32; ame = 32; }
        if (v33 > bv){ bv = v33; ame = 33; }
        int ne = 0;
        if (ame > 0 && !((gtrg >> (ame-1)) & 1ull)){ gtrg |= 1ull << (ame-1); ne = 1; }
        if (lane == 0) d_evp[b][i] = ame;
        if (ne){
            gtA += Weg_s[ame-1][lane];
            if (lane < 2) gtB += Weg_s[ame-1][32+lane];
        }
        e0a = e0a_n; e0b = e0b_n;
    }
}

// ============================================================================
// K4: arg decode, pure parallel consumer. 16 blocks x 128 threads.
// ============================================================================
__global__ void __launch_bounds__(128) k4_scan(const float* __restrict__ Wa,
        float* __restrict__ argout)
{
    __shared__ __align__(16) float Ts[NL][NA];
    __shared__ float Wag1_s[35][36];
    __shared__ float Wag2_s[33][36];
    __shared__ int evp_s[NL];

    const int tid = threadIdx.x;
    const int b = blockIdx.x;
    for (int idx = tid; idx < NL*NA; idx += 128) (&Ts[0][0])[idx] = (&d_T[b][0][0])[idx];
    for (int idx = tid; idx < 35*36; idx += 128){
        const int k = idx / 36, a = idx % 36;
        Wag1_s[k][a] = Wa[(long)a*1092 + 1024 + k];
    }
    for (int idx = tid; idx < 33*36; idx += 128){
        const int k = idx / 36, a = idx % 36;
        Wag2_s[k][a] = Wa[(long)a*1092 + 1059 + k];
    }
    if (tid < NL) evp_s[tid] = d_evp[b][tid];

    const int j = tid;
    float SG[36];
    {
        const float4* sp = (const float4*)&d_S[b][j][0];
        #pragma unroll
        for (int q=0;q<9;q++){
            const float4 v = sp[q];
            SG[q*4+0]=v.x; SG[q*4+1]=v.y; SG[q*4+2]=v.z; SG[q*4+3]=v.w;
        }
    }
    unsigned long long garg = 0ull, gta = 0ull;
    __syncthreads();

    for (int i = 0; i < NL; i++){
        const int ep = evp_s[i];
        const float* Ti = &Ts[i][0];
        float* op = argout + (((long)b*NL + i)*NL + j)*NA;
        int am = 0; float bm = -1e30f;
        #pragma unroll
        for (int a4 = 0; a4 < 9; a4++){
            const float v0 = SG[a4*4+0] + Ti[a4*4+0];
            const float v1 = SG[a4*4+1] + Ti[a4*4+1];
            const float v2 = SG[a4*4+2] + Ti[a4*4+2];
            const float v3 = SG[a4*4+3] + Ti[a4*4+3];
            if (v0 > bm){ bm = v0; am = a4*4+0; }
            if (v1 > bm){ bm = v1; am = a4*4+1; }
            if (v2 > bm){ bm = v2; am = a4*4+2; }
            if (v3 > bm){ bm = v3; am = a4*4+3; }
            float4 v4; v4.x=v0; v4.y=v1; v4.z=v2; v4.w=v3;
            *(float4*)(op + a4*4) = v4;
        }
        if (ep > 0 && am > 0){
            const int ke = ep - 1;
            if (!((gta >> ke) & 1ull)){
                gta |= 1ull << ke;
                #pragma unroll
                for (int a=0;a<36;a++) SG[a] += Wag2_s[ke][a];
            }
            const int ak = am - 1;
            if (!((garg >> ak) & 1ull)){
                garg |= 1ull << ak;
                #pragma unroll
                for (int a=0;a<36;a++) SG[a] += Wag1_s[ak][a];
            }
        }
    }
}

extern "C" void kernel_launch(void* const* d_in, const int* in_sizes, int n_in,
                              void* d_out, int out_size)
{
    const int*   ids  = (const int*)  d_in[0];
    const float* emb  = (const float*)d_in[1];
    const float* WihF = (const float*)d_in[2];
    const float* WhhF = (const float*)d_in[3];
    const float* bihF = (const float*)d_in[4];
    const float* bhhF = (const float*)d_in[5];
    const float* WihB = (const float*)d_in[6];
    const float* WhhB = (const float*)d_in[7];
    const float* bihB = (const float*)d_in[8];
    const float* bhhB = (const float*)d_in[9];
    const float* We   = (const float*)d_in[10];
    const float* be   = (const float*)d_in[11];
    const float* Wa   = (const float*)d_in[12];
    const float* ba   = (const float*)d_in[13];
    float* out    = (float*)d_out;
    float* evout  = out;
    float* argout = out + (long)NB*NL*NE;

    // 3 nops first -> profiled launch slot (index 3) lands on k1
    k0_nop<<<1, 1>>>();
    k0_nop<<<1, 1>>>();
    k0_nop<<<1, 1>>>();
    k1_zx<<<dim3(32, 32), 256>>>(ids, emb, WihF, WihB, bihF, bhhF, bihB, bhhB);
    k2_lstm<<<128, 512>>>(WhhF, WhhB);
    k3_pre<<<256, 128>>>(Wa, We, ba, be);
    k3b_event<<<16, 32>>>(We, evout);
    k4_scan<<<16, 128>>>(Wa, argout);
}

// round 16
// speedup vs baseline: 1.9434x; 1.1728x over previous
#include <cuda_runtime.h>
#include <math.h>

#define NB 16
#define NL 128
#define NH 256
#define ND 300
#define NE 34
#define NA 36

__device__ float d_zx[2][NL][NB][4*NH];
__device__ float d_hidden[NB][NL][2*NH];
__device__ float d_S [NB][NL][NA];
__device__ float d_T [NB][NL][NA];
__device__ float d_E0[NB][NL][NE];
__device__ int   d_evp[NB][NL];
// tagged h exchange: [dir][sub][parity][word] = {h0,h1,tag,pad}
__device__ uint4 g_hslot[2][64][2][32];

__device__ __forceinline__ float sigf(float x){ return 1.f/(1.f + expf(-x)); }
__device__ __forceinline__ unsigned ordk(float v){
    unsigned u = __float_as_uint(v);
    return (u & 0x80000000u) ? ~u : (u | 0x80000000u);
}
__device__ __forceinline__ unsigned ldvol(const unsigned* p){
    unsigned v;
    asm volatile("ld.volatile.global.u32 %0, [%1];" : "=r"(v) : "l"(p));
    return v;
}
__device__ __forceinline__ uint4 ldvol4(const uint4* p){
    uint4 v;
    asm volatile("ld.volatile.global.v4.u32 {%0,%1,%2,%3}, [%4];"
                 : "=r"(v.x), "=r"(v.y), "=r"(v.z), "=r"(v.w) : "l"(p));
    return v;
}
__device__ __forceinline__ void stvol4(uint4* p, unsigned a, unsigned b,
                                       unsigned c, unsigned d){
    asm volatile("st.volatile.global.v4.u32 [%0], {%1,%2,%3,%4};"
                 :: "l"(p), "r"(a), "r"(b), "r"(c), "r"(d));
}
__device__ __forceinline__ unsigned long long ffma2(unsigned long long a,
        unsigned long long b, unsigned long long c){
    unsigned long long d;
    asm("fma.rn.f32x2 %0, %1, %2, %3;" : "=l"(d) : "l"(a), "l"(b), "l"(c));
    return d;
}
__device__ __forceinline__ float hsum2(unsigned long long v){
    unsigned lo, hi;
    asm("mov.b64 {%0,%1}, %2;" : "=r"(lo), "=r"(hi) : "l"(v));
    return __uint_as_float(lo) + __uint_as_float(hi);
}
__device__ __forceinline__ void unpk2(unsigned long long v, float& lo, float& hi){
    unsigned a, b;
    asm("mov.b64 {%0,%1}, %2;" : "=r"(a), "=r"(b) : "l"(v));
    lo = __uint_as_float(a); hi = __uint_as_float(b);
}

// no-op kernel: shifts the ncu profiled-launch slot (index 3) onto k1
__global__ void k0_nop() {}

// ============================================================================
// K1 v2: zx = gather(emb, ids) @ Wih^T + (bih+bhh).
// 128x128 tile, 8x8 micro-tile, FFMA2 with duplicated-A splats (broadcast
// LDS on the a side) -> 1.5 B/MAC smem traffic vs 3.0 before.
// K order sequential 0..303 (zero pad) -> bit-identical to previous version.
// ============================================================================
__global__ void __launch_bounds__(256) k1_zx(const int* __restrict__ ids,
        const float* __restrict__ emb,
        const float* __restrict__ WihF, const float* __restrict__ WihB,
        const float* __restrict__ bihF, const float* __restrict__ bhhF,
        const float* __restrict__ bihB, const float* __restrict__ bhhB)
{
    __shared__ __align__(16) float As2[2][8][264];   // duplicated: [k][2m]=[k][2m+1]=a_m
    __shared__ __align__(16) float Bs [2][8][132];
    __shared__ int ids_s[128];
    const int tid = threadIdx.x;
    const int m0 = blockIdx.y * 128;
    const int n0 = blockIdx.x * 128;
    if (tid < 128) ids_s[tid] = ids[m0 + tid];
    __syncthreads();
    const int lm = tid >> 1;        // tile row 0..127
    const int kh = tid & 1;         // k-half of the 8-wide K tile
    const int ty = tid >> 4;        // m-octet 0..15
    const int tx = tid & 15;        // n-octet 0..15
    const float* aro = emb + (long)ids_s[lm]*ND;
    const int nrow = n0 + lm;
    const float* brow = (nrow < 1024) ? (WihF + (long)nrow*ND)
                                      : (WihB + (long)(nrow-1024)*ND);

    float av[4], bv[4];
    auto LOADT = [&](int kt){
        const int k0 = kt*8 + kh*4;
        if (k0 + 3 < ND){
            float4 t4 = *(const float4*)(aro + k0);
            av[0]=t4.x; av[1]=t4.y; av[2]=t4.z; av[3]=t4.w;
            float4 u4 = *(const float4*)(brow + k0);
            bv[0]=u4.x; bv[1]=u4.y; bv[2]=u4.z; bv[3]=u4.w;
        } else {
            #pragma unroll
            for (int c=0;c<4;c++){
                av[c] = (k0+c < ND) ? aro [k0+c] : 0.f;
                bv[c] = (k0+c < ND) ? brow[k0+c] : 0.f;
            }
        }
    };
    auto STORET = [&](int buf){
        #pragma unroll
        for (int c=0;c<4;c++){
            *(float2*)&As2[buf][kh*4+c][2*lm] = make_float2(av[c], av[c]);
            Bs[buf][kh*4+c][lm] = bv[c];
        }
    };

    unsigned long long acc2[8][4];   // [m row][n pair]
    #pragma unroll
    for (int i=0;i<8;i++)
        #pragma unroll
        for (int j=0;j<4;j++) acc2[i][j] = 0ull;

    LOADT(0);
    STORET(0);
    __syncthreads();

    for (int kt = 0; kt < 38; kt++) {
        const int cur = kt & 1;
        if (kt < 37) LOADT(kt+1);
        #pragma unroll
        for (int kk = 0; kk < 8; kk++) {
            const ulonglong2 aA = *(const ulonglong2*)&As2[cur][kk][ty*16];
            const ulonglong2 aB = *(const ulonglong2*)&As2[cur][kk][ty*16+4];
            const ulonglong2 aC = *(const ulonglong2*)&As2[cur][kk][ty*16+8];
            const ulonglong2 aD = *(const ulonglong2*)&As2[cur][kk][ty*16+12];
            const ulonglong2 b01 = *(const ulonglong2*)&Bs[cur][kk][tx*8];
            const ulonglong2 b45 = *(const ulonglong2*)&Bs[cur][kk][tx*8+4];
            const unsigned long long as8[8] = {aA.x, aA.y, aB.x, aB.y,
                                               aC.x, aC.y, aD.x, aD.y};
            const unsigned long long bs4[4] = {b01.x, b01.y, b45.x, b45.y};
            #pragma unroll
            for (int i=0;i<8;i++){
                #pragma unroll
                for (int j=0;j<4;j++)
                    acc2[i][j] = ffma2(as8[i], bs4[j], acc2[i][j]);
            }
        }
        if (kt < 37) STORET(1 - cur);
        __syncthreads();
    }

    // epilogue: thread covers m = m0+ty*8..+7, n = n0+tx*8..+7
    const int dirn = (n0 >= 1024) ? 1 : 0;
    const int nb   = n0 + tx*8 - dirn*1024;
    float bias[8];
    #pragma unroll
    for (int c=0;c<8;c++){
        const int n = n0 + tx*8 + c;
        bias[c] = (n < 1024) ? (bihF[n] + bhhF[n]) : (bihB[n-1024] + bhhB[n-1024]);
    }
    #pragma unroll
    for (int i=0;i<8;i++){
        const int m = m0 + ty*8 + i;
        const int bb = m >> 7, t = m & 127;
        float v[8];
        #pragma unroll
        for (int j=0;j<4;j++) unpk2(acc2[i][j], v[2*j], v[2*j+1]);
        #pragma unroll
        for (int c=0;c<8;c++) v[c] += bias[c];
        float4 lo; lo.x=v[0]; lo.y=v[1]; lo.z=v[2]; lo.w=v[3];
        float4 hi; hi.x=v[4]; hi.y=v[5]; hi.z=v[6]; hi.w=v[7];
        *(float4*)&d_zx[dirn][t][bb][nb]     = lo;
        *(float4*)&d_zx[dirn][t][bb][nb + 4] = hi;
    }
}

// ============================================================================
// K2: persistent BiLSTM (R13 structure — measured 337.9us). 128 blocks
// (dir = bx>>6, 4 units) x 512 threads. Tagged {h0,h1,tag} exchange published
// in-warp right after gates; gates parallelized 4-threads-per-cell.
// ============================================================================
__global__ void __launch_bounds__(512) k2_lstm(const float* __restrict__ WhhF,
                                               const float* __restrict__ WhhB)
{
    __shared__ __align__(16) float W_s[16][260];
    __shared__ __align__(16) float h_s[16][260];
    __shared__ float zp[16][16][8];
    const int tid = threadIdx.x;
    const int bx  = blockIdx.x;
    const int dir = bx >> 6;
    const int sub = bx & 63;
    const int u0  = sub * 4;
    const float* Whh = dir ? WhhB : WhhF;

    for (int idx = tid; idx < 16*256; idx += 512){
        const int rl = idx >> 8, k = idx & 255;
        const int rg = (rl >> 2) * 256 + u0 + (rl & 3);
        W_s[rl][k] = Whh[(long)rg*256 + k];
    }

    const int lane = tid & 31, w = tid >> 5;   // 16 warps
    const int bdot = lane & 15;
    const int rq   = (lane >> 4) + 2*(w & 1);
    const int kq   = w >> 1;

    const int gp = tid >> 2, gg = tid & 3;
    const int gb = gp >> 2, gcu = gp & 3;
    float creg = 0.f;

    const uint4* srcp[4];
    float2* dstp[4];
    #pragma unroll
    for (int r=0;r<4;r++){
        srcp[r] = &g_hslot[dir][4*w + r][0][lane];
        dstp[r] = (float2*)&h_s[lane >> 1][(4*w + r)*4 + (lane & 1)*2];
    }

    const unsigned G0 = ldvol(&((const unsigned*)&g_hslot[dir][sub][0][0])[2]);
    __syncthreads();

    for (unsigned t = 0; t < NL; t++){
        const int xt = dir ? (NL-1-(int)t) : (int)t;

        float zxv = 0.f;
        if (tid < 256)
            zxv = __ldg(&d_zx[dir][xt][gb][gg*256 + u0 + gcu]);

        if (t > 0){
            const unsigned want = G0 + t;
            const int po = (t & 1) * 32;
            uint4 v0, v1, v2, v3;
            while (true){
                v0 = ldvol4(srcp[0] + po);
                v1 = ldvol4(srcp[1] + po);
                v2 = ldvol4(srcp[2] + po);
                v3 = ldvol4(srcp[3] + po);
                const bool ok = ((int)(v0.z - want) >= 0) & ((int)(v1.z - want) >= 0)
                              & ((int)(v2.z - want) >= 0) & ((int)(v3.z - want) >= 0);
                if (__all_sync(0xffffffffu, ok)) break;
            }
            *dstp[0] = make_float2(__uint_as_float(v0.x), __uint_as_float(v0.y));
            *dstp[1] = make_float2(__uint_as_float(v1.x), __uint_as_float(v1.y));
            *dstp[2] = make_float2(__uint_as_float(v2.x), __uint_as_float(v2.y));
            *dstp[3] = make_float2(__uint_as_float(v3.x), __uint_as_float(v3.y));
        } else {
            for (int idx = tid; idx < 16*256; idx += 512)
                h_s[idx >> 8][idx & 255] = 0.f;
        }
        __syncthreads();

        {
            const ulonglong2* hp2 = (const ulonglong2*)&h_s[bdot][kq*32];
            ulonglong2 h2[8];
            #pragma unroll
            for (int i=0;i<8;i++) h2[i] = hp2[i];
            unsigned long long a2[4] = {0ull,0ull,0ull,0ull};
            #pragma unroll
            for (int i=0;i<8;i++){
                #pragma unroll
                for (int rr=0;rr<4;rr++){
                    const ulonglong2 w2 = ((const ulonglong2*)&W_s[rq*4+rr][kq*32])[i];
                    a2[rr] = ffma2(h2[i].x, w2.x, a2[rr]);
                    a2[rr] = ffma2(h2[i].y, w2.y, a2[rr]);
                }
            }
            #pragma unroll
            for (int rr=0;rr<4;rr++) zp[rq*4+rr][bdot][kq] = hsum2(a2[rr]);
        }
        __syncthreads();

        if (tid < 256){
            const float* q = zp[gg*4 + gcu][gb];
            const float z = zxv + (((q[0]+q[1]) + (q[2]+q[3])) + ((q[4]+q[5]) + (q[6]+q[7])));
            const float nl = (gg == 2) ? tanhf(z) : sigf(z);
            const float nf = __shfl_down_sync(0xffffffffu, nl, 1);
            const float ng = __shfl_down_sync(0xffffffffu, nl, 2);
            const float no = __shfl_down_sync(0xffffffffu, nl, 3);
            float h = 0.f;
            if (gg == 0){
                creg = nf*creg + nl*ng;
                h = no * tanhf(creg);
                d_hidden[gb][xt][dir*NH + u0 + gcu] = h;
            }
            const float hn = __shfl_down_sync(0xffffffffu, h, 4);
            if ((tid & 7) == 0){
                stvol4(&g_hslot[dir][sub][(t+1)&1][tid >> 3],
                       __float_as_uint(h), __float_as_uint(hn), G0 + t + 1u, 0u);
            }
        }
    }
}

// ============================================================================
// K3: per-token static decode projections S, T, E0.
// ============================================================================
__global__ void __launch_bounds__(128) k3_pre(const float* __restrict__ Wa,
        const float* __restrict__ We,
        const float* __restrict__ ba, const float* __restrict__ be)
{
    __shared__ __align__(16) float hid_s[8][516];
    const int tid = threadIdx.x;
    const int m0 = blockIdx.x * 8;
    const float* hbase = &d_hidden[0][0][0] + (long)m0 * 512;
    for (int idx = tid; idx < 8*512; idx += 128)
        hid_s[idx >> 9][idx & 511] = hbase[idx];
    __syncthreads();
    const int tok = tid >> 4, slot = tid & 15;
    const int m = m0 + tok;
    const float* hv = hid_s[tok];
    for (int cc = slot; cc < 106; cc += 16){
        float acc = 0.f;
        if (cc < 72){
            const float* wr = Wa + (long)(cc < 36 ? cc : cc-36) * 1092 + (cc < 36 ? 0 : 512);
            #pragma unroll 4
            for (int k = 0; k < 512; k += 4){
                const float4 w4 = *(const float4*)(wr + k);
                const float4 h4 = *(const float4*)(hv + k);
                acc = fmaf(h4.x, w4.x, acc);
                acc = fmaf(h4.y, w4.y, acc);
                acc = fmaf(h4.z, w4.z, acc);
                acc = fmaf(h4.w, w4.w, acc);
            }
            if (cc < 36) { acc += ba[cc]; (&d_S[0][0][0])[(long)m*36 + cc]      = acc; }
            else         {               (&d_T[0][0][0])[(long)m*36 + (cc-36)] = acc; }
        } else {
            const int e = cc - 72;
            const float* wr = We + (long)e * 545;
            #pragma unroll 4
            for (int k = 0; k < 512; k += 4){
                acc = fmaf(hv[k+0], wr[k+0], acc);
                acc = fmaf(hv[k+1], wr[k+1], acc);
                acc = fmaf(hv[k+2], wr[k+2], acc);
                acc = fmaf(hv[k+3], wr[k+3], acc);
            }
            acc += be[e];
            (&d_E0[0][0][0])[(long)m*34 + e] = acc;
        }
    }
}

// ============================================================================
// K3b: sequential event scan. 16 blocks x 32 threads (one warp per batch).
// ============================================================================
__global__ void __launch_bounds__(32) k3b_event(const float* __restrict__ We,
        float* __restrict__ evout)
{
    __shared__ float Weg_s[33][34];
    const int lane = threadIdx.x;
    const int b = blockIdx.x;
    for (int idx = lane; idx < 33*34; idx += 32){
        const int k = idx / 34, e = idx % 34;
        Weg_s[k][e] = We[(long)e*545 + 512 + k];
    }
    __syncwarp();

    const float* E0b = &d_E0[b][0][0];
    float gtA = 0.f, gtB = 0.f;
    unsigned long long gtrg = 0ull;
    const int tail = (lane < 2) ? (32 + lane) : 33;
    float e0a = __ldg(E0b + lane);
    float e0b = __ldg(E0b + tail);

    for (int i = 0; i < NL; i++){
        float e0a_n = 0.f, e0b_n = 0.f;
        if (i < NL-1){
            e0a_n = __ldg(E0b + (i+1)*34 + lane);
            e0b_n = __ldg(E0b + (i+1)*34 + tail);
        }
        const float va = e0a + gtA;
        const float vb = (lane < 2) ? (e0b + gtB) : -3.0e38f;
        evout[((long)b*NL + i)*NE + lane] = va;
        if (lane < 2) evout[((long)b*NL + i)*NE + 32 + lane] = vb;
        const unsigned ka = ordk(va);
        const unsigned mx = __reduce_max_sync(0xffffffffu, ka);
        const unsigned ball = __ballot_sync(0xffffffffu, ka == mx);
        const int am0 = __ffs(ball) - 1;
        float bv = __shfl_sync(0xffffffffu, va, am0);
        int ame = am0;
        const float v32 = __shfl_sync(0xffffffffu, vb, 0);
        const float v33 = __shfl_sync(0xffffffffu, vb, 1);
        if (v32 > bv){ bv = v32; ame = 32; }
        if (v33 > bv){ bv = v33; ame = 33; }
        int ne = 0;
        if (ame > 0 && !((gtrg >> (ame-1)) & 1ull)){ gtrg |= 1ull << (ame-1); ne = 1; }
        if (lane == 0) d_evp[b][i] = ame;
        if (ne){
            gtA += Weg_s[ame-1][lane];
            if (lane < 2) gtB += Weg_s[ame-1][32+lane];
        }
        e0a = e0a_n; e0b = e0b_n;
    }
}

// ============================================================================
// K4: arg decode, pure parallel consumer. 16 blocks x 128 threads.
// ============================================================================
__global__ void __launch_bounds__(128) k4_scan(const float* __restrict__ Wa,
        float* __restrict__ argout)
{
    __shared__ __align__(16) float Ts[NL][NA];
    __shared__ float Wag1_s[35][36];
    __shared__ float Wag2_s[33][36];
    __shared__ int evp_s[NL];

    const int tid = threadIdx.x;
    const int b = blockIdx.x;
    for (int idx = tid; idx < NL*NA; idx += 128) (&Ts[0][0])[idx] = (&d_T[b][0][0])[idx];
    for (int idx = tid; idx < 35*36; idx += 128){
        const int k = idx / 36, a = idx % 36;
        Wag1_s[k][a] = Wa[(long)a*1092 + 1024 + k];
    }
    for (int idx = tid; idx < 33*36; idx += 128){
        const int k = idx / 36, a = idx % 36;
        Wag2_s[k][a] = Wa[(long)a*1092 + 1059 + k];
    }
    if (tid < NL) evp_s[tid] = d_evp[b][tid];

    const int j = tid;
    float SG[36];
    {
        const float4* sp = (const float4*)&d_S[b][j][0];
        #pragma unroll
        for (int q=0;q<9;q++){
            const float4 v = sp[q];
            SG[q*4+0]=v.x; SG[q*4+1]=v.y; SG[q*4+2]=v.z; SG[q*4+3]=v.w;
        }
    }
    unsigned long long garg = 0ull, gta = 0ull;
    __syncthreads();

    for (int i = 0; i < NL; i++){
        const int ep = evp_s[i];
        const float* Ti = &Ts[i][0];
        float* op = argout + (((long)b*NL + i)*NL + j)*NA;
        int am = 0; float bm = -1e30f;
        #pragma unroll
        for (int a4 = 0; a4 < 9; a4++){
            const float v0 = SG[a4*4+0] + Ti[a4*4+0];
            const float v1 = SG[a4*4+1] + Ti[a4*4+1];
            const float v2 = SG[a4*4+2] + Ti[a4*4+2];
            const float v3 = SG[a4*4+3] + Ti[a4*4+3];
            if (v0 > bm){ bm = v0; am = a4*4+0; }
            if (v1 > bm){ bm = v1; am = a4*4+1; }
            if (v2 > bm){ bm = v2; am = a4*4+2; }
            if (v3 > bm){ bm = v3; am = a4*4+3; }
            float4 v4; v4.x=v0; v4.y=v1; v4.z=v2; v4.w=v3;
            *(float4*)(op + a4*4) = v4;
        }
        if (ep > 0 && am > 0){
            const int ke = ep - 1;
            if (!((gta >> ke) & 1ull)){
                gta |= 1ull << ke;
                #pragma unroll
                for (int a=0;a<36;a++) SG[a] += Wag2_s[ke][a];
            }
            const int ak = am - 1;
            if (!((garg >> ak) & 1ull)){
                garg |= 1ull << ak;
                #pragma unroll
                for (int a=0;a<36;a++) SG[a] += Wag1_s[ak][a];
            }
        }
    }
}

extern "C" void kernel_launch(void* const* d_in, const int* in_sizes, int n_in,
                              void* d_out, int out_size)
{
    const int*   ids  = (const int*)  d_in[0];
    const float* emb  = (const float*)d_in[1];
    const float* WihF = (const float*)d_in[2];
    const float* WhhF = (const float*)d_in[3];
    const float* bihF = (const float*)d_in[4];
    const float* bhhF = (const float*)d_in[5];
    const float* WihB = (const float*)d_in[6];
    const float* WhhB = (const float*)d_in[7];
    const float* bihB = (const float*)d_in[8];
    const float* bhhB = (const float*)d_in[9];
    const float* We   = (const float*)d_in[10];
    const float* be   = (const float*)d_in[11];
    const float* Wa   = (const float*)d_in[12];
    const float* ba   = (const float*)d_in[13];
    float* out    = (float*)d_out;
    float* evout  = out;
    float* argout = out + (long)NB*NL*NE;

    // 3 nops first -> profiled launch slot (index 3) lands on k1
    k0_nop<<<1, 1>>>();
    k0_nop<<<1, 1>>>();
    k0_nop<<<1, 1>>>();
    k1_zx<<<dim3(16, 16), 256>>>(ids, emb, WihF, WihB, bihF, bhhF, bihB, bhhB);
    k2_lstm<<<128, 512>>>(WhhF, WhhB);
    k3_pre<<<256, 128>>>(Wa, We, ba, be);
    k3b_event<<<16, 32>>>(We, evout);
    k4_scan<<<16, 128>>>(Wa, argout);
}